// round 2
// baseline (speedup 1.0000x reference)
#include <cuda_runtime.h>

#define N_TOK 8192
#define DIM   1024
#define NEXP  8
#define HID   256

// ---- static device scratch (no allocations allowed) ----
__device__ int   g_cursor[NEXP];
__device__ int   g_token[NEXP * N_TOK];
__device__ float g_gate [NEXP * N_TOK];
__device__ float g_h1[(size_t)NEXP * N_TOK * HID];   // 64 MB
__device__ float g_h2[(size_t)NEXP * N_TOK * HID];   // 64 MB

// ---------------------------------------------------------------------------
// init: zero output + cursors (must run every launch: graph replays)
// ---------------------------------------------------------------------------
__global__ void init_kernel(float* __restrict__ out) {
    size_t i = (size_t)blockIdx.x * blockDim.x + threadIdx.x;
    float4* o4 = (float4*)out;
    size_t tot = (size_t)N_TOK * DIM / 4;
    size_t stride = (size_t)gridDim.x * blockDim.x;
    for (size_t j = i; j < tot; j += stride)
        o4[j] = make_float4(0.f, 0.f, 0.f, 0.f);
    if (blockIdx.x == 0 && threadIdx.x < NEXP) g_cursor[threadIdx.x] = 0;
}

// ---------------------------------------------------------------------------
// gating: one warp per token. logits = x @ Wg + bg; softmax; top-2 scatter.
// ---------------------------------------------------------------------------
__global__ void gating_kernel(const float* __restrict__ x,
                              const float* __restrict__ Wg,
                              const float* __restrict__ bg) {
    int warp = threadIdx.x >> 5;
    int lane = threadIdx.x & 31;
    int n = blockIdx.x * 8 + warp;
    if (n >= N_TOK) return;

    float acc[NEXP];
#pragma unroll
    for (int e = 0; e < NEXP; e++) acc[e] = 0.f;

    const float* xr = x + (size_t)n * DIM;
    for (int d = lane; d < DIM; d += 32) {
        float xv = xr[d];
        const float4* w4 = (const float4*)(Wg + (size_t)d * NEXP);
        float4 wa = w4[0];
        float4 wb = w4[1];
        acc[0] += xv * wa.x; acc[1] += xv * wa.y;
        acc[2] += xv * wa.z; acc[3] += xv * wa.w;
        acc[4] += xv * wb.x; acc[5] += xv * wb.y;
        acc[6] += xv * wb.z; acc[7] += xv * wb.w;
    }
#pragma unroll
    for (int e = 0; e < NEXP; e++) {
#pragma unroll
        for (int off = 16; off > 0; off >>= 1)
            acc[e] += __shfl_xor_sync(0xffffffff, acc[e], off);
    }

    if (lane == 0) {
        float lg[NEXP];
        float mx = -1e30f;
#pragma unroll
        for (int e = 0; e < NEXP; e++) {
            lg[e] = acc[e] + bg[e];
            mx = fmaxf(mx, lg[e]);
        }
        float s = 0.f;
#pragma unroll
        for (int e = 0; e < NEXP; e++) {
            lg[e] = expf(lg[e] - mx);
            s += lg[e];
        }
        float inv = 1.f / s;

        int i0 = 0; float v0 = -1.f;
#pragma unroll
        for (int e = 0; e < NEXP; e++) {
            float p = lg[e] * inv;
            if (p > v0) { v0 = p; i0 = e; }
        }
        int i1 = -1; float v1 = -1.f;
#pragma unroll
        for (int e = 0; e < NEXP; e++) {
            if (e == i0) continue;
            float p = lg[e] * inv;
            if (p > v1) { v1 = p; i1 = e; }
        }
        int p0 = atomicAdd(&g_cursor[i0], 1);
        g_token[i0 * N_TOK + p0] = n;
        g_gate [i0 * N_TOK + p0] = v0;
        int p1 = atomicAdd(&g_cursor[i1], 1);
        g_token[i1 * N_TOK + p1] = n;
        g_gate [i1 * N_TOK + p1] = v1;
    }
}

// ---------------------------------------------------------------------------
// Tiled fp32 GEMMs: BM=64, BN=64, BK=16, 256 threads, 4x4 per thread.
// ---------------------------------------------------------------------------

#define FMA16()                                                                 \
    acc00 += a.x*b.x; acc01 += a.x*b.y; acc02 += a.x*b.z; acc03 += a.x*b.w;     \
    acc10 += a.y*b.x; acc11 += a.y*b.y; acc12 += a.y*b.z; acc13 += a.y*b.w;     \
    acc20 += a.z*b.x; acc21 += a.z*b.y; acc22 += a.z*b.z; acc23 += a.z*b.w;     \
    acc30 += a.w*b.x; acc31 += a.w*b.y; acc32 += a.w*b.z; acc33 += a.w*b.w;

// GEMM1: H1[m,:] = relu(x[token[m],:] @ W1[e] + b1[e])   (K=1024, N=256)
__global__ void __launch_bounds__(256)
gemm1_kernel(const float* __restrict__ x,
             const float* __restrict__ W1,
             const float* __restrict__ b1) {
    int e = blockIdx.z;
    int count = g_cursor[e];
    int m0 = blockIdx.x * 64;
    if (m0 >= count) return;
    int n0 = blockIdx.y * 64;

    __shared__ __align__(16) float As[16][64];
    __shared__ __align__(16) float Bs[16][64];
    __shared__ int rows[64];

    int t = threadIdx.x;
    if (t < 64) {
        int m = m0 + t;
        rows[t] = (m < count) ? g_token[e * N_TOK + m] : -1;
    }
    __syncthreads();

    const float* B = W1 + (size_t)e * DIM * HID;

    float acc00=0,acc01=0,acc02=0,acc03=0, acc10=0,acc11=0,acc12=0,acc13=0;
    float acc20=0,acc21=0,acc22=0,acc23=0, acc30=0,acc31=0,acc32=0,acc33=0;

    int ty = t >> 4, tx = t & 15;
    int la_m = t >> 2, la_k = (t & 3) * 4;
    int lb_k = t >> 4, lb_n = (t & 15) * 4;
    int r = rows[la_m];

    for (int k0 = 0; k0 < DIM; k0 += 16) {
        float4 av = (r >= 0) ? *(const float4*)(x + (size_t)r * DIM + k0 + la_k)
                             : make_float4(0.f, 0.f, 0.f, 0.f);
        As[la_k + 0][la_m] = av.x;
        As[la_k + 1][la_m] = av.y;
        As[la_k + 2][la_m] = av.z;
        As[la_k + 3][la_m] = av.w;
        *(float4*)&Bs[lb_k][lb_n] =
            *(const float4*)(B + (size_t)(k0 + lb_k) * HID + n0 + lb_n);
        __syncthreads();
#pragma unroll
        for (int k = 0; k < 16; k++) {
            float4 a = *(const float4*)&As[k][ty * 4];
            float4 b = *(const float4*)&Bs[k][tx * 4];
            FMA16();
        }
        __syncthreads();
    }

    float4 bias = *(const float4*)(b1 + e * HID + n0 + tx * 4);
#pragma unroll
    for (int i = 0; i < 4; i++) {
        int m = m0 + ty * 4 + i;
        if (m < count) {
            float v0, v1, v2, v3;
            if (i == 0) { v0=acc00; v1=acc01; v2=acc02; v3=acc03; }
            else if (i == 1) { v0=acc10; v1=acc11; v2=acc12; v3=acc13; }
            else if (i == 2) { v0=acc20; v1=acc21; v2=acc22; v3=acc23; }
            else { v0=acc30; v1=acc31; v2=acc32; v3=acc33; }
            float4 o;
            o.x = fmaxf(v0 + bias.x, 0.f);
            o.y = fmaxf(v1 + bias.y, 0.f);
            o.z = fmaxf(v2 + bias.z, 0.f);
            o.w = fmaxf(v3 + bias.w, 0.f);
            *(float4*)(g_h1 + ((size_t)e * N_TOK + m) * HID + n0 + tx * 4) = o;
        }
    }
}

// GEMM2: H2 = relu(H1 @ W2[e] + b2[e])   (K=256, N=256)
__global__ void __launch_bounds__(256)
gemm2_kernel(const float* __restrict__ W2,
             const float* __restrict__ b2) {
    int e = blockIdx.z;
    int count = g_cursor[e];
    int m0 = blockIdx.x * 64;
    if (m0 >= count) return;
    int n0 = blockIdx.y * 64;

    __shared__ __align__(16) float As[16][64];
    __shared__ __align__(16) float Bs[16][64];

    int t = threadIdx.x;
    const float* A = g_h1 + (size_t)e * N_TOK * HID;
    const float* B = W2 + (size_t)e * HID * HID;

    float acc00=0,acc01=0,acc02=0,acc03=0, acc10=0,acc11=0,acc12=0,acc13=0;
    float acc20=0,acc21=0,acc22=0,acc23=0, acc30=0,acc31=0,acc32=0,acc33=0;

    int ty = t >> 4, tx = t & 15;
    int la_m = t >> 2, la_k = (t & 3) * 4;
    int lb_k = t >> 4, lb_n = (t & 15) * 4;
    int ma = m0 + la_m;

    for (int k0 = 0; k0 < HID; k0 += 16) {
        float4 av = (ma < count) ? *(const float4*)(A + (size_t)ma * HID + k0 + la_k)
                                 : make_float4(0.f, 0.f, 0.f, 0.f);
        As[la_k + 0][la_m] = av.x;
        As[la_k + 1][la_m] = av.y;
        As[la_k + 2][la_m] = av.z;
        As[la_k + 3][la_m] = av.w;
        *(float4*)&Bs[lb_k][lb_n] =
            *(const float4*)(B + (size_t)(k0 + lb_k) * HID + n0 + lb_n);
        __syncthreads();
#pragma unroll
        for (int k = 0; k < 16; k++) {
            float4 a = *(const float4*)&As[k][ty * 4];
            float4 b = *(const float4*)&Bs[k][tx * 4];
            FMA16();
        }
        __syncthreads();
    }

    float4 bias = *(const float4*)(b2 + e * HID + n0 + tx * 4);
#pragma unroll
    for (int i = 0; i < 4; i++) {
        int m = m0 + ty * 4 + i;
        if (m < count) {
            float v0, v1, v2, v3;
            if (i == 0) { v0=acc00; v1=acc01; v2=acc02; v3=acc03; }
            else if (i == 1) { v0=acc10; v1=acc11; v2=acc12; v3=acc13; }
            else if (i == 2) { v0=acc20; v1=acc21; v2=acc22; v3=acc23; }
            else { v0=acc30; v1=acc31; v2=acc32; v3=acc33; }
            float4 o;
            o.x = fmaxf(v0 + bias.x, 0.f);
            o.y = fmaxf(v1 + bias.y, 0.f);
            o.z = fmaxf(v2 + bias.z, 0.f);
            o.w = fmaxf(v3 + bias.w, 0.f);
            *(float4*)(g_h2 + ((size_t)e * N_TOK + m) * HID + n0 + tx * 4) = o;
        }
    }
}

// GEMM3: out[token,:] += gate * relu(H2 @ W3[e] + b3[e])   (K=256, N=1024)
__global__ void __launch_bounds__(256)
gemm3_kernel(const float* __restrict__ W3,
             const float* __restrict__ b3,
             float* __restrict__ out) {
    int e = blockIdx.z;
    int count = g_cursor[e];
    int m0 = blockIdx.x * 64;
    if (m0 >= count) return;
    int n0 = blockIdx.y * 64;

    __shared__ __align__(16) float As[16][64];
    __shared__ __align__(16) float Bs[16][64];

    int t = threadIdx.x;
    const float* A = g_h2 + (size_t)e * N_TOK * HID;
    const float* B = W3 + (size_t)e * HID * DIM;

    float acc00=0,acc01=0,acc02=0,acc03=0, acc10=0,acc11=0,acc12=0,acc13=0;
    float acc20=0,acc21=0,acc22=0,acc23=0, acc30=0,acc31=0,acc32=0,acc33=0;

    int ty = t >> 4, tx = t & 15;
    int la_m = t >> 2, la_k = (t & 3) * 4;
    int lb_k = t >> 4, lb_n = (t & 15) * 4;
    int ma = m0 + la_m;

    for (int k0 = 0; k0 < HID; k0 += 16) {
        float4 av = (ma < count) ? *(const float4*)(A + (size_t)ma * HID + k0 + la_k)
                                 : make_float4(0.f, 0.f, 0.f, 0.f);
        As[la_k + 0][la_m] = av.x;
        As[la_k + 1][la_m] = av.y;
        As[la_k + 2][la_m] = av.z;
        As[la_k + 3][la_m] = av.w;
        *(float4*)&Bs[lb_k][lb_n] =
            *(const float4*)(B + (size_t)(k0 + lb_k) * DIM + n0 + lb_n);
        __syncthreads();
#pragma unroll
        for (int k = 0; k < 16; k++) {
            float4 a = *(const float4*)&As[k][ty * 4];
            float4 b = *(const float4*)&Bs[k][tx * 4];
            FMA16();
        }
        __syncthreads();
    }

    float4 bias = *(const float4*)(b3 + e * DIM + n0 + tx * 4);
#pragma unroll
    for (int i = 0; i < 4; i++) {
        int m = m0 + ty * 4 + i;
        if (m < count) {
            int token = g_token[e * N_TOK + m];
            float gate = g_gate[e * N_TOK + m];
            float v0, v1, v2, v3;
            if (i == 0) { v0=acc00; v1=acc01; v2=acc02; v3=acc03; }
            else if (i == 1) { v0=acc10; v1=acc11; v2=acc12; v3=acc13; }
            else if (i == 2) { v0=acc20; v1=acc21; v2=acc22; v3=acc23; }
            else { v0=acc30; v1=acc31; v2=acc32; v3=acc33; }
            float* o = out + (size_t)token * DIM + n0 + tx * 4;
            atomicAdd(&o[0], gate * fmaxf(v0 + bias.x, 0.f));
            atomicAdd(&o[1], gate * fmaxf(v1 + bias.y, 0.f));
            atomicAdd(&o[2], gate * fmaxf(v2 + bias.z, 0.f));
            atomicAdd(&o[3], gate * fmaxf(v3 + bias.w, 0.f));
        }
    }
}

// ---------------------------------------------------------------------------
extern "C" void kernel_launch(void* const* d_in, const int* in_sizes, int n_in,
                              void* d_out, int out_size) {
    const float* x  = (const float*)d_in[0];
    const float* Wg = (const float*)d_in[1];
    const float* bg = (const float*)d_in[2];
    const float* W1 = (const float*)d_in[3];
    const float* b1 = (const float*)d_in[4];
    const float* W2 = (const float*)d_in[5];
    const float* b2 = (const float*)d_in[6];
    const float* W3 = (const float*)d_in[7];
    const float* b3 = (const float*)d_in[8];
    float* out = (float*)d_out;

    init_kernel<<<1024, 256>>>(out);
    gating_kernel<<<N_TOK / 8, 256>>>(x, Wg, bg);
    gemm1_kernel<<<dim3(128, 4, 8), 256>>>(x, W1, b1);
    gemm2_kernel<<<dim3(128, 4, 8), 256>>>(W2, b2);
    gemm3_kernel<<<dim3(128, 16, 8), 256>>>(W3, b3, out);
}

// round 3
// speedup vs baseline: 2.0060x; 2.0060x over previous
#include <cuda_runtime.h>
#include <cstdint>

#define N_TOK 8192
#define DIM   1024
#define NEXP  8
#define HID   256

#define BM 128
#define BN 64
#define BK 16
#define LDA 20   // As row stride in floats (pad: conflict-free ldmatrix)
#define LDB 20   // Bs row stride in floats

// ---- static device scratch (no allocations allowed) ----
__device__ int   g_cursor[NEXP];
__device__ int   g_token[NEXP * N_TOK];
__device__ float g_gate [NEXP * N_TOK];
__device__ int   g_slot [2 * N_TOK];
__device__ float g_h1[(size_t)NEXP * N_TOK * HID];   // 64 MB
__device__ float g_h2[(size_t)NEXP * N_TOK * HID];   // 64 MB
__device__ float g_eo[(size_t)NEXP * N_TOK * DIM];   // 256 MB (sparse-touched)

// ---------------------------------------------------------------------------
__global__ void init_kernel() {
    if (threadIdx.x < NEXP) g_cursor[threadIdx.x] = 0;
}

// ---------------------------------------------------------------------------
// gating: one warp per token. logits = x @ Wg + bg; softmax; top-2 scatter.
// ---------------------------------------------------------------------------
__global__ void gating_kernel(const float* __restrict__ x,
                              const float* __restrict__ Wg,
                              const float* __restrict__ bg) {
    int warp = threadIdx.x >> 5;
    int lane = threadIdx.x & 31;
    int n = blockIdx.x * 8 + warp;
    if (n >= N_TOK) return;

    float acc[NEXP];
#pragma unroll
    for (int e = 0; e < NEXP; e++) acc[e] = 0.f;

    const float* xr = x + (size_t)n * DIM;
    for (int d = lane; d < DIM; d += 32) {
        float xv = xr[d];
        const float4* w4 = (const float4*)(Wg + (size_t)d * NEXP);
        float4 wa = w4[0];
        float4 wb = w4[1];
        acc[0] += xv * wa.x; acc[1] += xv * wa.y;
        acc[2] += xv * wa.z; acc[3] += xv * wa.w;
        acc[4] += xv * wb.x; acc[5] += xv * wb.y;
        acc[6] += xv * wb.z; acc[7] += xv * wb.w;
    }
#pragma unroll
    for (int e = 0; e < NEXP; e++) {
#pragma unroll
        for (int off = 16; off > 0; off >>= 1)
            acc[e] += __shfl_xor_sync(0xffffffff, acc[e], off);
    }

    if (lane == 0) {
        float lg[NEXP];
        float mx = -1e30f;
#pragma unroll
        for (int e = 0; e < NEXP; e++) {
            lg[e] = acc[e] + bg[e];
            mx = fmaxf(mx, lg[e]);
        }
        float s = 0.f;
#pragma unroll
        for (int e = 0; e < NEXP; e++) {
            lg[e] = expf(lg[e] - mx);
            s += lg[e];
        }
        float inv = 1.f / s;

        int i0 = 0; float v0 = -1.f;
#pragma unroll
        for (int e = 0; e < NEXP; e++) {
            float p = lg[e] * inv;
            if (p > v0) { v0 = p; i0 = e; }
        }
        int i1 = -1; float v1 = -1.f;
#pragma unroll
        for (int e = 0; e < NEXP; e++) {
            if (e == i0) continue;
            float p = lg[e] * inv;
            if (p > v1) { v1 = p; i1 = e; }
        }
        int p0 = atomicAdd(&g_cursor[i0], 1);
        g_token[i0 * N_TOK + p0] = n;
        g_gate [i0 * N_TOK + p0] = v0;
        g_slot [n] = i0 * N_TOK + p0;
        int p1 = atomicAdd(&g_cursor[i1], 1);
        g_token[i1 * N_TOK + p1] = n;
        g_gate [i1 * N_TOK + p1] = v1;
        g_slot [N_TOK + n] = i1 * N_TOK + p1;
    }
}

// ---------------------------------------------------------------------------
// TF32 tensor-core helpers
// ---------------------------------------------------------------------------
__device__ __forceinline__ float cvt_tf32(float x) {
    unsigned u;
    asm("cvt.rna.tf32.f32 %0, %1;" : "=r"(u) : "f"(x));
    return __uint_as_float(u);
}

__device__ __forceinline__ void ldsm_x4(unsigned addr, unsigned r[4]) {
    asm volatile("ldmatrix.sync.aligned.m8n8.x4.shared.b16 {%0,%1,%2,%3}, [%4];"
                 : "=r"(r[0]), "=r"(r[1]), "=r"(r[2]), "=r"(r[3]) : "r"(addr));
}

__device__ __forceinline__ void mma_tf32(float c[4], const unsigned a[4],
                                         unsigned b0, unsigned b1) {
    asm volatile(
        "mma.sync.aligned.m16n8k8.row.col.f32.tf32.tf32.f32 "
        "{%0,%1,%2,%3}, {%4,%5,%6,%7}, {%8,%9}, {%0,%1,%2,%3};"
        : "+f"(c[0]), "+f"(c[1]), "+f"(c[2]), "+f"(c[3])
        : "r"(a[0]), "r"(a[1]), "r"(a[2]), "r"(a[3]), "r"(b0), "r"(b1));
}

// ---------------------------------------------------------------------------
// GEMM: Out[BMxBN tile] = act(A[128xK] @ B[KxN] + bias), tf32 mma.
//   MODE 0: A = x gathered by g_token, Out = g_h1 (relu)
//   MODE 1: A = g_h1, Out = g_h2 (relu)
//   MODE 2: A = g_h2, Out = g_eo (gate * relu)
// ---------------------------------------------------------------------------
template <int KDIM, int NMAT, int MODE>
__global__ void __launch_bounds__(256)
gemm_mma(const float* __restrict__ A,
         const float* __restrict__ Bmat,
         const float* __restrict__ bias,
         float* __restrict__ Out) {
    int e = blockIdx.z;
    int count = g_cursor[e];
    int m0 = blockIdx.x * BM;
    if (m0 >= count) return;
    int n0 = blockIdx.y * BN;

    __shared__ __align__(16) float As[2][BM * LDA];
    __shared__ __align__(16) float Bs[2][BN * LDB];
    __shared__ int rows[BM];

    int t = threadIdx.x;
    int lane = t & 31;
    int w = t >> 5;
    int wm = w & 3;        // 4 m-warps
    int wn = w >> 2;       // 2 n-warps

    const float* A_e = (MODE == 0) ? A : A + (size_t)e * N_TOK * HID;
    const float* B_e = Bmat + (size_t)e * KDIM * NMAT;

    if (MODE == 0) {
        if (t < BM) {
            int pos = m0 + t;
            if (pos >= count) pos = count - 1;
            rows[t] = g_token[e * N_TOK + pos];
        }
        __syncthreads();
    }

    // ---- load-to-register helpers (A: 2 float4; B: 4 scalars -> float4) ----
    int ar[2], ac4[2];
#pragma unroll
    for (int j = 0; j < 2; j++) {
        int fidx = t + 256 * j;
        ar[j]  = fidx >> 2;
        ac4[j] = (fidx & 3) << 2;
    }
    int bn = t & 63;
    int bk4 = (t >> 6) << 2;

    float4 va[2];
    float4 vb;

    auto load_regs = [&](int k0) {
#pragma unroll
        for (int j = 0; j < 2; j++) {
            const float* src;
            if (MODE == 0)
                src = A_e + (size_t)rows[ar[j]] * KDIM + k0 + ac4[j];
            else
                src = A_e + (size_t)(m0 + ar[j]) * KDIM + k0 + ac4[j];
            float4 v = *(const float4*)src;
            va[j].x = cvt_tf32(v.x); va[j].y = cvt_tf32(v.y);
            va[j].z = cvt_tf32(v.z); va[j].w = cvt_tf32(v.w);
        }
        const float* bsrc = B_e + (size_t)(k0 + bk4) * NMAT + n0 + bn;
        vb.x = cvt_tf32(bsrc[0]);
        vb.y = cvt_tf32(bsrc[(size_t)NMAT]);
        vb.z = cvt_tf32(bsrc[(size_t)2 * NMAT]);
        vb.w = cvt_tf32(bsrc[(size_t)3 * NMAT]);
    };
    auto store_smem = [&](int buf) {
#pragma unroll
        for (int j = 0; j < 2; j++)
            *(float4*)&As[buf][ar[j] * LDA + ac4[j]] = va[j];
        *(float4*)&Bs[buf][bn * LDB + bk4] = vb;
    };

    // ---- ldmatrix lane addressing (precomputed) ----
    unsigned asb[2], bsb[2];
#pragma unroll
    for (int b = 0; b < 2; b++) {
        asb[b] = (unsigned)__cvta_generic_to_shared(&As[b][0]);
        bsb[b] = (unsigned)__cvta_generic_to_shared(&Bs[b][0]);
    }
    int a_row_off = (lane & 15);
    int a_k_off   = (lane >> 4) << 2;
    int b_row_off = (lane & 7) + ((lane >> 4) << 3);
    int b_k_off   = ((lane >> 3) & 1) << 2;

    float c[2][4][4];
#pragma unroll
    for (int mi = 0; mi < 2; mi++)
#pragma unroll
        for (int ni = 0; ni < 4; ni++)
#pragma unroll
            for (int r = 0; r < 4; r++) c[mi][ni][r] = 0.f;

    const int NK = KDIM / BK;

    load_regs(0);
    store_smem(0);
    __syncthreads();

    for (int kt = 0; kt < NK; kt++) {
        int cur = kt & 1;
        if (kt + 1 < NK) load_regs((kt + 1) * BK);

#pragma unroll
        for (int ka = 0; ka < BK; ka += 8) {
            unsigned afrag[2][4], bfrag[2][4];
#pragma unroll
            for (int mi = 0; mi < 2; mi++) {
                unsigned addr = asb[cur] +
                    ((wm * 32 + mi * 16 + a_row_off) * LDA + ka + a_k_off) * 4;
                ldsm_x4(addr, afrag[mi]);
            }
#pragma unroll
            for (int p = 0; p < 2; p++) {
                unsigned addr = bsb[cur] +
                    ((wn * 32 + p * 16 + b_row_off) * LDB + ka + b_k_off) * 4;
                ldsm_x4(addr, bfrag[p]);
            }
#pragma unroll
            for (int mi = 0; mi < 2; mi++) {
#pragma unroll
                for (int p = 0; p < 2; p++) {
                    mma_tf32(c[mi][2 * p + 0], afrag[mi], bfrag[p][0], bfrag[p][1]);
                    mma_tf32(c[mi][2 * p + 1], afrag[mi], bfrag[p][2], bfrag[p][3]);
                }
            }
        }

        if (kt + 1 < NK) store_smem((kt + 1) & 1);
        __syncthreads();
    }

    // ---- epilogue ----
    const float* bias_e = bias + (size_t)e * NMAT;
    int g  = lane >> 2;
    int tc = lane & 3;

#pragma unroll
    for (int mi = 0; mi < 2; mi++) {
#pragma unroll
        for (int h = 0; h < 2; h++) {
            int m_local = wm * 32 + mi * 16 + g + h * 8;
            int pos = m0 + m_local;
            if (pos < count) {
                float gate = 0.f;
                size_t orow;
                if (MODE == 2) {
                    gate = g_gate[e * N_TOK + pos];
                    orow = ((size_t)e * N_TOK + pos) * DIM;
                } else {
                    orow = ((size_t)e * N_TOK + pos) * HID;
                }
#pragma unroll
                for (int ni = 0; ni < 4; ni++) {
                    int n = n0 + wn * 32 + ni * 8 + tc * 2;
                    float v0 = c[mi][ni][h * 2 + 0];
                    float v1 = c[mi][ni][h * 2 + 1];
                    float2 bv = *(const float2*)(bias_e + n);
                    float2 o;
                    if (MODE == 2) {
                        o.x = gate * fmaxf(v0 + bv.x, 0.f);
                        o.y = gate * fmaxf(v1 + bv.y, 0.f);
                    } else {
                        o.x = fmaxf(v0 + bv.x, 0.f);
                        o.y = fmaxf(v1 + bv.y, 0.f);
                    }
                    *(float2*)(Out + orow + n) = o;
                }
            }
        }
    }
}

// ---------------------------------------------------------------------------
// combine: out[n,:] = eo[slot0[n],:] + eo[slot1[n],:]
// ---------------------------------------------------------------------------
__global__ void combine_kernel(float* __restrict__ out) {
    const float4* e4 = (const float4*)g_eo;
    float4* o4 = (float4*)out;
    int tot = N_TOK * (DIM / 4);
    int stride = gridDim.x * blockDim.x;
    for (int idx = blockIdx.x * blockDim.x + threadIdx.x; idx < tot; idx += stride) {
        int n = idx >> 8;           // DIM/4 = 256
        int cidx = idx & 255;
        int s0 = g_slot[n];
        int s1 = g_slot[N_TOK + n];
        float4 a = e4[(size_t)s0 * (DIM / 4) + cidx];
        float4 b = e4[(size_t)s1 * (DIM / 4) + cidx];
        float4 o;
        o.x = a.x + b.x; o.y = a.y + b.y; o.z = a.z + b.z; o.w = a.w + b.w;
        o4[idx] = o;
    }
}

// ---------------------------------------------------------------------------
extern "C" void kernel_launch(void* const* d_in, const int* in_sizes, int n_in,
                              void* d_out, int out_size) {
    const float* x  = (const float*)d_in[0];
    const float* Wg = (const float*)d_in[1];
    const float* bg = (const float*)d_in[2];
    const float* W1 = (const float*)d_in[3];
    const float* b1 = (const float*)d_in[4];
    const float* W2 = (const float*)d_in[5];
    const float* b2 = (const float*)d_in[6];
    const float* W3 = (const float*)d_in[7];
    const float* b3 = (const float*)d_in[8];
    float* out = (float*)d_out;

    init_kernel<<<1, 32>>>();
    gating_kernel<<<N_TOK / 8, 256>>>(x, Wg, bg);

    float* h1 = nullptr, *h2 = nullptr, *eo = nullptr;
    cudaGetSymbolAddress((void**)&h1, g_h1);
    cudaGetSymbolAddress((void**)&h2, g_h2);
    cudaGetSymbolAddress((void**)&eo, g_eo);

    gemm_mma<DIM, HID, 0><<<dim3(N_TOK / BM, HID / BN, NEXP), 256>>>(x,  W1, b1, h1);
    gemm_mma<HID, HID, 1><<<dim3(N_TOK / BM, HID / BN, NEXP), 256>>>(h1, W2, b2, h2);
    gemm_mma<HID, DIM, 2><<<dim3(N_TOK / BM, DIM / BN, NEXP), 256>>>(h2, W3, b3, eo);
    combine_kernel<<<2048, 256>>>(out);
}

// round 8
// speedup vs baseline: 2.5563x; 1.2744x over previous
#include <cuda_runtime.h>
#include <cstdint>

#define N_TOK 8192
#define DIM   1024
#define NEXP  8
#define HID   256

#define BM 128
#define BN 128
#define BK 16
#define LDA 20   // padded row stride (floats): conflict-free ldmatrix, 80B = 5x16B
#define LDB 20

// ---- static device scratch (no allocations allowed) ----
__device__ int   g_cursor[NEXP];
__device__ int   g_token[NEXP * N_TOK];
__device__ float g_gate [NEXP * N_TOK];
__device__ int   g_slot [2 * N_TOK];
__device__ float g_h1[(size_t)NEXP * N_TOK * HID];     // 64 MB (tf32-rounded)
__device__ float g_h2[(size_t)NEXP * N_TOK * HID];     // 64 MB (tf32-rounded)
__device__ float g_eo[(size_t)NEXP * N_TOK * DIM];     // 256 MB (sparse-touched)
__device__ float g_w1t[(size_t)NEXP * DIM * HID];      // 8 MB  [e][N][K] rounded
__device__ float g_w2t[(size_t)NEXP * HID * HID];      // 2 MB
__device__ float g_w3t[(size_t)NEXP * HID * DIM];      // 8 MB

// ---------------------------------------------------------------------------
__device__ __forceinline__ float cvt_tf32(float x) {
    unsigned u;
    asm("cvt.rna.tf32.f32 %0, %1;" : "=r"(u) : "f"(x));
    return __uint_as_float(u);
}
__device__ __forceinline__ void ldsm_x4(unsigned addr, unsigned r[4]) {
    asm volatile("ldmatrix.sync.aligned.m8n8.x4.shared.b16 {%0,%1,%2,%3}, [%4];"
                 : "=r"(r[0]), "=r"(r[1]), "=r"(r[2]), "=r"(r[3]) : "r"(addr));
}
__device__ __forceinline__ void mma_tf32(float c[4], const unsigned a[4],
                                         unsigned b0, unsigned b1) {
    asm volatile(
        "mma.sync.aligned.m16n8k8.row.col.f32.tf32.tf32.f32 "
        "{%0,%1,%2,%3}, {%4,%5,%6,%7}, {%8,%9}, {%0,%1,%2,%3};"
        : "+f"(c[0]), "+f"(c[1]), "+f"(c[2]), "+f"(c[3])
        : "r"(a[0]), "r"(a[1]), "r"(a[2]), "r"(a[3]), "r"(b0), "r"(b1));
}

// ---------------------------------------------------------------------------
__global__ void init_kernel() {
    if (threadIdx.x < NEXP) g_cursor[threadIdx.x] = 0;
}

// transpose + round: src [e][KD][ND] -> dst [e][ND][KD]
template <int KD, int ND>
__global__ void transpose_round(const float* __restrict__ src,
                                float* __restrict__ dst) {
    __shared__ float tile[32][33];
    int e = blockIdx.z;
    const float* s = src + (size_t)e * KD * ND;
    float* d = dst + (size_t)e * KD * ND;
    int k0 = blockIdx.x * 32, n0 = blockIdx.y * 32;
    int tx = threadIdx.x & 31, ty = threadIdx.x >> 5;
#pragma unroll
    for (int r = ty; r < 32; r += 8)
        tile[r][tx] = s[(size_t)(k0 + r) * ND + n0 + tx];
    __syncthreads();
#pragma unroll
    for (int r = ty; r < 32; r += 8)
        d[(size_t)(n0 + r) * KD + k0 + tx] = cvt_tf32(tile[tx][r]);
}

// ---------------------------------------------------------------------------
// gating: one warp per token (uses ORIGINAL fp32 x)
// ---------------------------------------------------------------------------
__global__ void gating_kernel(const float* __restrict__ x,
                              const float* __restrict__ Wg,
                              const float* __restrict__ bg) {
    int warp = threadIdx.x >> 5;
    int lane = threadIdx.x & 31;
    int n = blockIdx.x * 8 + warp;
    if (n >= N_TOK) return;

    float acc[NEXP];
#pragma unroll
    for (int e = 0; e < NEXP; e++) acc[e] = 0.f;

    const float* xr = x + (size_t)n * DIM;
    for (int d = lane; d < DIM; d += 32) {
        float xv = xr[d];
        const float4* w4 = (const float4*)(Wg + (size_t)d * NEXP);
        float4 wa = w4[0];
        float4 wb = w4[1];
        acc[0] += xv * wa.x; acc[1] += xv * wa.y;
        acc[2] += xv * wa.z; acc[3] += xv * wa.w;
        acc[4] += xv * wb.x; acc[5] += xv * wb.y;
        acc[6] += xv * wb.z; acc[7] += xv * wb.w;
    }
#pragma unroll
    for (int e = 0; e < NEXP; e++) {
#pragma unroll
        for (int off = 16; off > 0; off >>= 1)
            acc[e] += __shfl_xor_sync(0xffffffff, acc[e], off);
    }

    if (lane == 0) {
        float lg[NEXP];
        float mx = -1e30f;
#pragma unroll
        for (int e = 0; e < NEXP; e++) {
            lg[e] = acc[e] + bg[e];
            mx = fmaxf(mx, lg[e]);
        }
        float s = 0.f;
#pragma unroll
        for (int e = 0; e < NEXP; e++) {
            lg[e] = expf(lg[e] - mx);
            s += lg[e];
        }
        float inv = 1.f / s;

        int i0 = 0; float v0 = -1.f;
#pragma unroll
        for (int e = 0; e < NEXP; e++) {
            float p = lg[e] * inv;
            if (p > v0) { v0 = p; i0 = e; }
        }
        int i1 = -1; float v1 = -1.f;
#pragma unroll
        for (int e = 0; e < NEXP; e++) {
            if (e == i0) continue;
            float p = lg[e] * inv;
            if (p > v1) { v1 = p; i1 = e; }
        }
        int p0 = atomicAdd(&g_cursor[i0], 1);
        g_token[i0 * N_TOK + p0] = n;
        g_gate [i0 * N_TOK + p0] = v0;
        g_slot [n] = i0 * N_TOK + p0;
        int p1 = atomicAdd(&g_cursor[i1], 1);
        g_token[i1 * N_TOK + p1] = n;
        g_gate [i1 * N_TOK + p1] = v1;
        g_slot [N_TOK + n] = i1 * N_TOK + p1;
    }
}

// ---------------------------------------------------------------------------
// HMMA tf32 GEMM: CTA tile 128x128xK, 8 warps (4m x 2n), warptile 32x64.
// Register-staged double-buffered smem (NO cp.async). B pre-transposed [N][K].
//   MODE 0: A = x gathered by g_token (cvt inline) -> g_h1 (relu, rounded)
//   MODE 1: A = g_h1                               -> g_h2 (relu, rounded)
//   MODE 2: A = g_h2                               -> g_eo (gate*relu, fp32)
// ---------------------------------------------------------------------------
template <int KDIM, int NMAT, int MODE>
__global__ void __launch_bounds__(256)
gemm_mma(const float* __restrict__ A,
         const float* __restrict__ Bt,     // [e][NMAT][KDIM] transposed weights
         const float* __restrict__ bias,
         float* __restrict__ Out) {
    int e = blockIdx.z;
    int count = g_cursor[e];
    int m0 = blockIdx.x * BM;
    if (m0 >= count) return;
    int n0 = blockIdx.y * BN;

    __shared__ __align__(16) float As[2][BM * LDA];
    __shared__ __align__(16) float Bs[2][BN * LDB];
    __shared__ int rows[BM];

    int t = threadIdx.x;
    int lane = t & 31;
    int w = t >> 5;
    int wm = w & 3;
    int wn = w >> 2;

    const float* A_e = (MODE == 0) ? A : A + (size_t)e * N_TOK * HID;
    const float* B_e = Bt + (size_t)e * (size_t)KDIM * NMAT;

    if (MODE == 0 && t < BM) {
        int pos = m0 + t;
        if (pos >= count) pos = count - 1;
        rows[t] = g_token[e * N_TOK + pos];
    }
    __syncthreads();

    // per-thread load tasks: A 512 float4 (2/thr), B 512 float4 (2/thr)
    int a_row[2], a_seg[2];
#pragma unroll
    for (int q = 0; q < 2; q++) {
        int s = t + 256 * q;
        a_row[q] = s >> 2;          // 0..127
        a_seg[q] = (s & 3) * 4;     // float offset within 16-float row chunk
    }
    const float* a_src_row[2];
    const float* b_src_row[2];
#pragma unroll
    for (int q = 0; q < 2; q++) {
        if (MODE == 0) a_src_row[q] = A_e + (size_t)rows[a_row[q]] * KDIM;
        else           a_src_row[q] = A_e + (size_t)(m0 + a_row[q]) * KDIM;
        b_src_row[q] = B_e + (size_t)(n0 + a_row[q]) * KDIM;
    }

    float4 va[2], vb[2];
    auto load_regs = [&](int kt) {
        int k0 = kt * BK;
#pragma unroll
        for (int q = 0; q < 2; q++) {
            float4 v = *(const float4*)(a_src_row[q] + k0 + a_seg[q]);
            if (MODE == 0) {
                v.x = cvt_tf32(v.x); v.y = cvt_tf32(v.y);
                v.z = cvt_tf32(v.z); v.w = cvt_tf32(v.w);
            }
            va[q] = v;
            vb[q] = *(const float4*)(b_src_row[q] + k0 + a_seg[q]);
        }
    };
    auto store_smem = [&](int buf) {
#pragma unroll
        for (int q = 0; q < 2; q++) {
            *(float4*)&As[buf][a_row[q] * LDA + a_seg[q]] = va[q];
            *(float4*)&Bs[buf][a_row[q] * LDB + a_seg[q]] = vb[q];
        }
    };

    // ldmatrix lane addressing
    unsigned asb[2], bsb[2];
#pragma unroll
    for (int b = 0; b < 2; b++) {
        asb[b] = (unsigned)__cvta_generic_to_shared(&As[b][0]);
        bsb[b] = (unsigned)__cvta_generic_to_shared(&Bs[b][0]);
    }
    int a_row_off = lane & 15;
    int a_k_off   = (lane >> 4) << 2;
    int b_row_off = (lane & 7) + ((lane >> 4) << 3);
    int b_k_off   = ((lane >> 3) & 1) << 2;

    float c[2][8][4];
#pragma unroll
    for (int mi = 0; mi < 2; mi++)
#pragma unroll
        for (int ni = 0; ni < 8; ni++)
#pragma unroll
            for (int r = 0; r < 4; r++) c[mi][ni][r] = 0.f;

    const int NK = KDIM / BK;
    load_regs(0);
    store_smem(0);
    __syncthreads();

    for (int kt = 0; kt < NK; kt++) {
        int cur = kt & 1;
        if (kt + 1 < NK) load_regs(kt + 1);

#pragma unroll
        for (int ka = 0; ka < BK; ka += 8) {
            unsigned afrag[2][4], bfrag[4][4];
#pragma unroll
            for (int mi = 0; mi < 2; mi++) {
                unsigned addr = asb[cur] +
                    ((wm * 32 + mi * 16 + a_row_off) * LDA + ka + a_k_off) * 4;
                ldsm_x4(addr, afrag[mi]);
            }
#pragma unroll
            for (int p = 0; p < 4; p++) {
                unsigned addr = bsb[cur] +
                    ((wn * 64 + p * 16 + b_row_off) * LDB + ka + b_k_off) * 4;
                ldsm_x4(addr, bfrag[p]);
            }
#pragma unroll
            for (int mi = 0; mi < 2; mi++) {
#pragma unroll
                for (int p = 0; p < 4; p++) {
                    mma_tf32(c[mi][2 * p + 0], afrag[mi], bfrag[p][0], bfrag[p][1]);
                    mma_tf32(c[mi][2 * p + 1], afrag[mi], bfrag[p][2], bfrag[p][3]);
                }
            }
        }

        if (kt + 1 < NK) store_smem((kt + 1) & 1);
        __syncthreads();
    }

    // ---- epilogue ----
    const float* bias_e = bias + (size_t)e * NMAT;
    int g  = lane >> 2;
    int tc = lane & 3;

#pragma unroll
    for (int mi = 0; mi < 2; mi++) {
#pragma unroll
        for (int h = 0; h < 2; h++) {
            int m_local = wm * 32 + mi * 16 + g + h * 8;
            int pos = m0 + m_local;
            if (pos < count) {
                float gate = 1.f;
                size_t orow;
                if (MODE == 2) {
                    gate = g_gate[e * N_TOK + pos];
                    orow = ((size_t)e * N_TOK + pos) * DIM;
                } else {
                    orow = ((size_t)e * N_TOK + pos) * HID;
                }
#pragma unroll
                for (int ni = 0; ni < 8; ni++) {
                    int n = n0 + wn * 64 + ni * 8 + tc * 2;
                    float v0 = c[mi][ni][h * 2 + 0];
                    float v1 = c[mi][ni][h * 2 + 1];
                    float2 bv = *(const float2*)(bias_e + n);
                    float2 o;
                    if (MODE == 2) {
                        o.x = gate * fmaxf(v0 + bv.x, 0.f);
                        o.y = gate * fmaxf(v1 + bv.y, 0.f);
                    } else {
                        o.x = cvt_tf32(fmaxf(v0 + bv.x, 0.f));
                        o.y = cvt_tf32(fmaxf(v1 + bv.y, 0.f));
                    }
                    *(float2*)(Out + orow + n) = o;
                }
            }
        }
    }
}

// ---------------------------------------------------------------------------
// combine: out[n,:] = eo[slot0[n],:] + eo[slot1[n],:]
// ---------------------------------------------------------------------------
__global__ void combine_kernel(float* __restrict__ out) {
    const float4* e4 = (const float4*)g_eo;
    float4* o4 = (float4*)out;
    int tot = N_TOK * (DIM / 4);
    int stride = gridDim.x * blockDim.x;
    for (int idx = blockIdx.x * blockDim.x + threadIdx.x; idx < tot; idx += stride) {
        int n = idx >> 8;           // DIM/4 = 256
        int cidx = idx & 255;
        int s0 = g_slot[n];
        int s1 = g_slot[N_TOK + n];
        float4 a = e4[(size_t)s0 * (DIM / 4) + cidx];
        float4 b = e4[(size_t)s1 * (DIM / 4) + cidx];
        float4 o;
        o.x = a.x + b.x; o.y = a.y + b.y; o.z = a.z + b.z; o.w = a.w + b.w;
        o4[idx] = o;
    }
}

// ---------------------------------------------------------------------------
extern "C" void kernel_launch(void* const* d_in, const int* in_sizes, int n_in,
                              void* d_out, int out_size) {
    const float* x  = (const float*)d_in[0];
    const float* Wg = (const float*)d_in[1];
    const float* bg = (const float*)d_in[2];
    const float* W1 = (const float*)d_in[3];
    const float* b1 = (const float*)d_in[4];
    const float* W2 = (const float*)d_in[5];
    const float* b2 = (const float*)d_in[6];
    const float* W3 = (const float*)d_in[7];
    const float* b3 = (const float*)d_in[8];
    float* out = (float*)d_out;

    float *h1, *h2, *eo, *w1t, *w2t, *w3t;
    cudaGetSymbolAddress((void**)&h1,  g_h1);
    cudaGetSymbolAddress((void**)&h2,  g_h2);
    cudaGetSymbolAddress((void**)&eo,  g_eo);
    cudaGetSymbolAddress((void**)&w1t, g_w1t);
    cudaGetSymbolAddress((void**)&w2t, g_w2t);
    cudaGetSymbolAddress((void**)&w3t, g_w3t);

    init_kernel<<<1, 32>>>();
    transpose_round<DIM, HID><<<dim3(DIM / 32, HID / 32, NEXP), 256>>>(W1, w1t);
    transpose_round<HID, HID><<<dim3(HID / 32, HID / 32, NEXP), 256>>>(W2, w2t);
    transpose_round<HID, DIM><<<dim3(HID / 32, DIM / 32, NEXP), 256>>>(W3, w3t);
    gating_kernel<<<N_TOK / 8, 256>>>(x, Wg, bg);

    gemm_mma<DIM, HID, 0><<<dim3(N_TOK / BM, HID / BN, NEXP), 256>>>(x,  w1t, b1, h1);
    gemm_mma<HID, HID, 1><<<dim3(N_TOK / BM, HID / BN, NEXP), 256>>>(h1, w2t, b2, h2);
    gemm_mma<HID, DIM, 2><<<dim3(N_TOK / BM, DIM / BN, NEXP), 256>>>(h2, w3t, b3, eo);
    combine_kernel<<<2048, 256>>>(out);
}

// round 9
// speedup vs baseline: 3.6650x; 1.4337x over previous
#include <cuda_runtime.h>
#include <cuda_fp16.h>
#include <cstdint>

#define N_TOK 8192
#define DIM   1024
#define NEXP  8
#define HID   256

#define BM 128
#define BN 128
#define BK 32    // K elements per tile (2 x k16 mma steps)
#define LDA 40   // padded row stride in halves: 80B = 5x16B, conflict-free ldmatrix
#define LDB 40

// ---- static device scratch (no allocations allowed) ----
__device__ int    g_cursor[NEXP];
__device__ int    g_token[NEXP * N_TOK];
__device__ float  g_gate [NEXP * N_TOK];
__device__ int    g_slot [2 * N_TOK];
__device__ __half g_h1h[(size_t)NEXP * N_TOK * HID];   // 32 MB
__device__ __half g_h2h[(size_t)NEXP * N_TOK * HID];   // 32 MB
__device__ __half g_eoh[(size_t)NEXP * N_TOK * DIM];   // 128 MB (sparse-touched)
__device__ __half g_w1t[(size_t)NEXP * DIM * HID];     // 4 MB  [e][N][K] half
__device__ __half g_w2t[(size_t)NEXP * HID * HID];     // 1 MB
__device__ __half g_w3t[(size_t)NEXP * HID * DIM];     // 4 MB

// ---------------------------------------------------------------------------
__device__ __forceinline__ void ldsm_x4(unsigned addr, unsigned r[4]) {
    asm volatile("ldmatrix.sync.aligned.m8n8.x4.shared.b16 {%0,%1,%2,%3}, [%4];"
                 : "=r"(r[0]), "=r"(r[1]), "=r"(r[2]), "=r"(r[3]) : "r"(addr));
}
__device__ __forceinline__ void mma_f16(float c[4], const unsigned a[4],
                                        unsigned b0, unsigned b1) {
    asm volatile(
        "mma.sync.aligned.m16n8k16.row.col.f32.f16.f16.f32 "
        "{%0,%1,%2,%3}, {%4,%5,%6,%7}, {%8,%9}, {%0,%1,%2,%3};"
        : "+f"(c[0]), "+f"(c[1]), "+f"(c[2]), "+f"(c[3])
        : "r"(a[0]), "r"(a[1]), "r"(a[2]), "r"(a[3]), "r"(b0), "r"(b1));
}
__device__ __forceinline__ unsigned pack_h2(float x, float y) {
    __half2 h = __floats2half2_rn(x, y);
    return *(unsigned*)&h;
}

// ---------------------------------------------------------------------------
__global__ void init_kernel() {
    if (threadIdx.x < NEXP) g_cursor[threadIdx.x] = 0;
}

// transpose + convert: src [e][KD][ND] fp32 -> dst [e][ND][KD] half
template <int KD, int ND>
__global__ void transpose_half(const float* __restrict__ src,
                               __half* __restrict__ dst) {
    __shared__ float tile[32][33];
    int e = blockIdx.z;
    const float* s = src + (size_t)e * KD * ND;
    __half* d = dst + (size_t)e * KD * ND;
    int k0 = blockIdx.x * 32, n0 = blockIdx.y * 32;
    int tx = threadIdx.x & 31, ty = threadIdx.x >> 5;
#pragma unroll
    for (int r = ty; r < 32; r += 8)
        tile[r][tx] = s[(size_t)(k0 + r) * ND + n0 + tx];
    __syncthreads();
#pragma unroll
    for (int r = ty; r < 32; r += 8)
        d[(size_t)(n0 + r) * KD + k0 + tx] = __float2half_rn(tile[tx][r]);
}

// ---------------------------------------------------------------------------
// gating: one warp per token (uses ORIGINAL fp32 x)
// ---------------------------------------------------------------------------
__global__ void gating_kernel(const float* __restrict__ x,
                              const float* __restrict__ Wg,
                              const float* __restrict__ bg) {
    int warp = threadIdx.x >> 5;
    int lane = threadIdx.x & 31;
    int n = blockIdx.x * 8 + warp;
    if (n >= N_TOK) return;

    float acc[NEXP];
#pragma unroll
    for (int e = 0; e < NEXP; e++) acc[e] = 0.f;

    const float* xr = x + (size_t)n * DIM;
    for (int d = lane; d < DIM; d += 32) {
        float xv = xr[d];
        const float4* w4 = (const float4*)(Wg + (size_t)d * NEXP);
        float4 wa = w4[0];
        float4 wb = w4[1];
        acc[0] += xv * wa.x; acc[1] += xv * wa.y;
        acc[2] += xv * wa.z; acc[3] += xv * wa.w;
        acc[4] += xv * wb.x; acc[5] += xv * wb.y;
        acc[6] += xv * wb.z; acc[7] += xv * wb.w;
    }
#pragma unroll
    for (int e = 0; e < NEXP; e++) {
#pragma unroll
        for (int off = 16; off > 0; off >>= 1)
            acc[e] += __shfl_xor_sync(0xffffffff, acc[e], off);
    }

    if (lane == 0) {
        float lg[NEXP];
        float mx = -1e30f;
#pragma unroll
        for (int e = 0; e < NEXP; e++) {
            lg[e] = acc[e] + bg[e];
            mx = fmaxf(mx, lg[e]);
        }
        float s = 0.f;
#pragma unroll
        for (int e = 0; e < NEXP; e++) {
            lg[e] = expf(lg[e] - mx);
            s += lg[e];
        }
        float inv = 1.f / s;

        int i0 = 0; float v0 = -1.f;
#pragma unroll
        for (int e = 0; e < NEXP; e++) {
            float p = lg[e] * inv;
            if (p > v0) { v0 = p; i0 = e; }
        }
        int i1 = -1; float v1 = -1.f;
#pragma unroll
        for (int e = 0; e < NEXP; e++) {
            if (e == i0) continue;
            float p = lg[e] * inv;
            if (p > v1) { v1 = p; i1 = e; }
        }
        int p0 = atomicAdd(&g_cursor[i0], 1);
        g_token[i0 * N_TOK + p0] = n;
        g_gate [i0 * N_TOK + p0] = v0;
        g_slot [n] = i0 * N_TOK + p0;
        int p1 = atomicAdd(&g_cursor[i1], 1);
        g_token[i1 * N_TOK + p1] = n;
        g_gate [i1 * N_TOK + p1] = v1;
        g_slot [N_TOK + n] = i1 * N_TOK + p1;
    }
}

// ---------------------------------------------------------------------------
// fp16 HMMA GEMM: CTA tile 128x128xK, 8 warps (4m x 2n), warptile 32x64.
// m16n8k16.f32.f16.f16.f32, register-staged double-buffered smem (no cp.async).
//   MODE 0: A = x fp32 gathered by g_token (cvt inline) -> g_h1h (relu, half)
//   MODE 1: A = g_h1h                                   -> g_h2h (relu, half)
//   MODE 2: A = g_h2h                                   -> g_eoh (gate*relu, half)
// ---------------------------------------------------------------------------
template <int KDIM, int NMAT, int MODE>
__global__ void __launch_bounds__(256)
gemm_mma(const float* __restrict__ Af,      // fp32 source (MODE 0)
         const __half* __restrict__ Ah,     // half source (MODE 1/2)
         const __half* __restrict__ Bt,     // [e][NMAT][KDIM] half weights
         const float* __restrict__ bias,
         __half* __restrict__ Out) {
    int e = blockIdx.z;
    int count = g_cursor[e];
    int m0 = blockIdx.x * BM;
    if (m0 >= count) return;
    int n0 = blockIdx.y * BN;

    __shared__ __align__(16) __half As[2][BM * LDA];
    __shared__ __align__(16) __half Bs[2][BN * LDB];
    __shared__ int rows[BM];

    int t = threadIdx.x;
    int lane = t & 31;
    int w = t >> 5;
    int wm = w & 3;
    int wn = w >> 2;

    const __half* A_eh = Ah + (size_t)e * N_TOK * HID;
    const __half* B_e  = Bt + (size_t)e * (size_t)KDIM * NMAT;

    if (MODE == 0 && t < BM) {
        int pos = m0 + t;
        if (pos >= count) pos = count - 1;
        rows[t] = g_token[e * N_TOK + pos];
    }
    __syncthreads();

    // per-thread load tasks: 512 16B-segs (8 halves) each for A and B, 2/thr
    int a_row[2], a_seg[2];
#pragma unroll
    for (int q = 0; q < 2; q++) {
        int s = t + 256 * q;
        a_row[q] = s >> 2;          // 0..127
        a_seg[q] = (s & 3) * 8;     // half-offset within 32-half row chunk
    }
    const float*  a_srcf[2];
    const __half* a_srch[2];
    const __half* b_src [2];
#pragma unroll
    for (int q = 0; q < 2; q++) {
        if (MODE == 0) a_srcf[q] = Af + (size_t)rows[a_row[q]] * KDIM;
        else           a_srch[q] = A_eh + (size_t)(m0 + a_row[q]) * KDIM;
        b_src[q] = B_e + (size_t)(n0 + a_row[q]) * KDIM;
    }

    uint4 va[2], vb[2];
    auto load_regs = [&](int kt) {
        int k0 = kt * BK;
#pragma unroll
        for (int q = 0; q < 2; q++) {
            if (MODE == 0) {
                float4 v0 = *(const float4*)(a_srcf[q] + k0 + a_seg[q]);
                float4 v1 = *(const float4*)(a_srcf[q] + k0 + a_seg[q] + 4);
                va[q].x = pack_h2(v0.x, v0.y);
                va[q].y = pack_h2(v0.z, v0.w);
                va[q].z = pack_h2(v1.x, v1.y);
                va[q].w = pack_h2(v1.z, v1.w);
            } else {
                va[q] = *(const uint4*)(a_srch[q] + k0 + a_seg[q]);
            }
            vb[q] = *(const uint4*)(b_src[q] + k0 + a_seg[q]);
        }
    };
    auto store_smem = [&](int buf) {
#pragma unroll
        for (int q = 0; q < 2; q++) {
            *(uint4*)&As[buf][a_row[q] * LDA + a_seg[q]] = va[q];
            *(uint4*)&Bs[buf][a_row[q] * LDB + a_seg[q]] = vb[q];
        }
    };

    unsigned asb[2], bsb[2];
#pragma unroll
    for (int b = 0; b < 2; b++) {
        asb[b] = (unsigned)__cvta_generic_to_shared(&As[b][0]);
        bsb[b] = (unsigned)__cvta_generic_to_shared(&Bs[b][0]);
    }
    int rsel = lane & 15;           // row within 16-row block
    int ksel = (lane >> 4) * 8;     // half-offset: 0 or 8

    float c[2][8][4];
#pragma unroll
    for (int mi = 0; mi < 2; mi++)
#pragma unroll
        for (int ni = 0; ni < 8; ni++)
#pragma unroll
            for (int r = 0; r < 4; r++) c[mi][ni][r] = 0.f;

    const int NK = KDIM / BK;
    load_regs(0);
    store_smem(0);
    __syncthreads();

    for (int kt = 0; kt < NK; kt++) {
        int cur = kt & 1;
        if (kt + 1 < NK) load_regs(kt + 1);

#pragma unroll
        for (int ka = 0; ka < BK; ka += 16) {
            unsigned afrag[2][4], bfrag[4][4];
#pragma unroll
            for (int mi = 0; mi < 2; mi++) {
                unsigned addr = asb[cur] +
                    ((wm * 32 + mi * 16 + rsel) * LDA + ka + ksel) * 2;
                ldsm_x4(addr, afrag[mi]);
            }
#pragma unroll
            for (int p = 0; p < 4; p++) {
                unsigned addr = bsb[cur] +
                    ((wn * 64 + p * 16 + rsel) * LDB + ka + ksel) * 2;
                ldsm_x4(addr, bfrag[p]);
            }
#pragma unroll
            for (int mi = 0; mi < 2; mi++) {
#pragma unroll
                for (int p = 0; p < 4; p++) {
                    // bfrag[p]: r0=n0-7@k0-7, r1=n8-15@k0-7, r2=n0-7@k8-15, r3=n8-15@k8-15
                    mma_f16(c[mi][2 * p + 0], afrag[mi], bfrag[p][0], bfrag[p][2]);
                    mma_f16(c[mi][2 * p + 1], afrag[mi], bfrag[p][1], bfrag[p][3]);
                }
            }
        }

        if (kt + 1 < NK) store_smem((kt + 1) & 1);
        __syncthreads();
    }

    // ---- epilogue: packed half2 stores ----
    const float* bias_e = bias + (size_t)e * NMAT;
    int g  = lane >> 2;
    int tc = lane & 3;

#pragma unroll
    for (int mi = 0; mi < 2; mi++) {
#pragma unroll
        for (int h = 0; h < 2; h++) {
            int m_local = wm * 32 + mi * 16 + g + h * 8;
            int pos = m0 + m_local;
            if (pos < count) {
                float gate = 1.f;
                size_t orow;
                if (MODE == 2) {
                    gate = g_gate[e * N_TOK + pos];
                    orow = ((size_t)e * N_TOK + pos) * DIM;
                } else {
                    orow = ((size_t)e * N_TOK + pos) * HID;
                }
#pragma unroll
                for (int ni = 0; ni < 8; ni++) {
                    int n = n0 + wn * 64 + ni * 8 + tc * 2;
                    float v0 = c[mi][ni][h * 2 + 0];
                    float v1 = c[mi][ni][h * 2 + 1];
                    float2 bv = *(const float2*)(bias_e + n);
                    float o0, o1;
                    if (MODE == 2) {
                        o0 = gate * fmaxf(v0 + bv.x, 0.f);
                        o1 = gate * fmaxf(v1 + bv.y, 0.f);
                    } else {
                        o0 = fmaxf(v0 + bv.x, 0.f);
                        o1 = fmaxf(v1 + bv.y, 0.f);
                    }
                    *(unsigned*)(Out + orow + n) = pack_h2(o0, o1);
                }
            }
        }
    }
}

// ---------------------------------------------------------------------------
// combine: out[n,:] = eo[slot0[n],:] + eo[slot1[n],:]  (half -> fp32)
// ---------------------------------------------------------------------------
__global__ void combine_kernel(float* __restrict__ out) {
    const __half* eo = g_eoh;
    int tot = N_TOK * (DIM / 8);
    int stride = gridDim.x * blockDim.x;
    for (int idx = blockIdx.x * blockDim.x + threadIdx.x; idx < tot; idx += stride) {
        int n = idx >> 7;           // DIM/8 = 128
        int cidx = (idx & 127) * 8;
        int s0 = g_slot[n];
        int s1 = g_slot[N_TOK + n];
        uint4 a4 = *(const uint4*)(eo + (size_t)s0 * DIM + cidx);
        uint4 b4 = *(const uint4*)(eo + (size_t)s1 * DIM + cidx);
        const __half2* ah = (const __half2*)&a4;
        const __half2* bh = (const __half2*)&b4;
        float4 o0, o1;
        float2 t0 = __half22float2(ah[0]), u0 = __half22float2(bh[0]);
        float2 t1 = __half22float2(ah[1]), u1 = __half22float2(bh[1]);
        float2 t2 = __half22float2(ah[2]), u2 = __half22float2(bh[2]);
        float2 t3 = __half22float2(ah[3]), u3 = __half22float2(bh[3]);
        o0.x = t0.x + u0.x; o0.y = t0.y + u0.y;
        o0.z = t1.x + u1.x; o0.w = t1.y + u1.y;
        o1.x = t2.x + u2.x; o1.y = t2.y + u2.y;
        o1.z = t3.x + u3.x; o1.w = t3.y + u3.y;
        float* op = out + (size_t)n * DIM + cidx;
        *(float4*)(op + 0) = o0;
        *(float4*)(op + 4) = o1;
    }
}

// ---------------------------------------------------------------------------
extern "C" void kernel_launch(void* const* d_in, const int* in_sizes, int n_in,
                              void* d_out, int out_size) {
    const float* x  = (const float*)d_in[0];
    const float* Wg = (const float*)d_in[1];
    const float* bg = (const float*)d_in[2];
    const float* W1 = (const float*)d_in[3];
    const float* b1 = (const float*)d_in[4];
    const float* W2 = (const float*)d_in[5];
    const float* b2 = (const float*)d_in[6];
    const float* W3 = (const float*)d_in[7];
    const float* b3 = (const float*)d_in[8];
    float* out = (float*)d_out;

    __half *h1, *h2, *eo, *w1t, *w2t, *w3t;
    cudaGetSymbolAddress((void**)&h1,  g_h1h);
    cudaGetSymbolAddress((void**)&h2,  g_h2h);
    cudaGetSymbolAddress((void**)&eo,  g_eoh);
    cudaGetSymbolAddress((void**)&w1t, g_w1t);
    cudaGetSymbolAddress((void**)&w2t, g_w2t);
    cudaGetSymbolAddress((void**)&w3t, g_w3t);

    init_kernel<<<1, 32>>>();
    transpose_half<DIM, HID><<<dim3(DIM / 32, HID / 32, NEXP), 256>>>(W1, w1t);
    transpose_half<HID, HID><<<dim3(HID / 32, HID / 32, NEXP), 256>>>(W2, w2t);
    transpose_half<HID, DIM><<<dim3(HID / 32, DIM / 32, NEXP), 256>>>(W3, w3t);
    gating_kernel<<<N_TOK / 8, 256>>>(x, Wg, bg);

    gemm_mma<DIM, HID, 0><<<dim3(N_TOK / BM, HID / BN, NEXP), 256>>>(x, h1, w1t, b1, h1);
    gemm_mma<HID, HID, 1><<<dim3(N_TOK / BM, HID / BN, NEXP), 256>>>(nullptr, h1, w2t, b2, h2);
    gemm_mma<HID, DIM, 2><<<dim3(N_TOK / BM, DIM / BN, NEXP), 256>>>(nullptr, h2, w3t, b3, eo);
    combine_kernel<<<2048, 256>>>(out);
}